// round 2
// baseline (speedup 1.0000x reference)
#include <cuda_runtime.h>
#include <math.h>

#define BATCH 8
#define SEQ   1024
#define DIMC  512
#define NH    8
#define HD    64
#define ROWS  (BATCH*SEQ)           // 8192
#define QKVC  (3*DIMC)              // 1536
#define ATT_SCALE 0.125f            // HD^-0.5
#define NEG_MAX (-3.402823466e38f)  // float32 finfo.min

// Scratch (allocation-free rule: __device__ globals)
__device__ float g_qkv[(size_t)ROWS * QKVC];   // [8192, 1536]
__device__ float g_att[(size_t)ROWS * DIMC];   // [8192, 512]  (b,t, h*d)

// ---------------------------------------------------------------------------
// C[M,N] = A[M,K] @ W[N,K]^T + bias[N]   (all fp32, M,N multiples of 64, K mult of 16)
// 64x64 block tile, BK=16, 256 threads, 4x4 micro-tile per thread.
// ---------------------------------------------------------------------------
__global__ __launch_bounds__(256)
void gemm_bias_kernel(const float* __restrict__ A,
                      const float* __restrict__ W,
                      const float* __restrict__ bias,
                      float* __restrict__ C,
                      int M, int N, int K) {
    __shared__ float As[64][17];
    __shared__ float Bs[64][17];
    const int tid = threadIdx.x;
    const int tx = tid & 15, ty = tid >> 4;
    const int row0 = blockIdx.x << 6;
    const int col0 = blockIdx.y << 6;
    const int lr = tid >> 2;          // 0..63
    const int lc = (tid & 3) << 2;    // 0,4,8,12

    float acc[4][4] = {};

    for (int k0 = 0; k0 < K; k0 += 16) {
        float4 a4 = *(const float4*)(A + (size_t)(row0 + lr) * K + k0 + lc);
        float4 b4 = *(const float4*)(W + (size_t)(col0 + lr) * K + k0 + lc);
        As[lr][lc+0] = a4.x; As[lr][lc+1] = a4.y; As[lr][lc+2] = a4.z; As[lr][lc+3] = a4.w;
        Bs[lr][lc+0] = b4.x; Bs[lr][lc+1] = b4.y; Bs[lr][lc+2] = b4.z; Bs[lr][lc+3] = b4.w;
        __syncthreads();
        #pragma unroll
        for (int kk = 0; kk < 16; kk++) {
            float a[4], b[4];
            #pragma unroll
            for (int i = 0; i < 4; i++) a[i] = As[ty*4+i][kk];
            #pragma unroll
            for (int j = 0; j < 4; j++) b[j] = Bs[tx*4+j][kk];
            #pragma unroll
            for (int i = 0; i < 4; i++)
                #pragma unroll
                for (int j = 0; j < 4; j++)
                    acc[i][j] = fmaf(a[i], b[j], acc[i][j]);
        }
        __syncthreads();
    }

    #pragma unroll
    for (int j = 0; j < 4; j++) {
        float bj = bias[col0 + tx*4 + j];
        #pragma unroll
        for (int i = 0; i < 4; i++)
            C[(size_t)(row0 + ty*4 + i) * N + col0 + tx*4 + j] = acc[i][j] + bj;
    }
}

// ---------------------------------------------------------------------------
// Flash attention: one block = 64 queries of one (b,h). Streams 64-wide K/V
// tiles with online softmax. Mask (int32) != 0 -> score = -FLT_MAX pre-softmax,
// reproducing jnp.where(mask, finfo.min, scores) incl. all-masked -> uniform.
// Output written in [b, t, h*HD + d] layout (the (0,2,1,3) transpose).
// Dynamic smem: Qs/Ks/Vs/Ps each 64x65 fp32 = 66560 B total.
// ---------------------------------------------------------------------------
__global__ __launch_bounds__(256)
void attn_kernel(const float* __restrict__ qkv,
                 const int* __restrict__ mask,
                 float* __restrict__ out) {
    extern __shared__ float sm[];
    float* Qs = sm;                 // [64][65]
    float* Ks = sm + 64*65;         // [64][65]
    float* Vs = sm + 2*64*65;       // [64][65]
    float* Ps = sm + 3*64*65;       // [64][65]

    const int tid = threadIdx.x;
    const int tx = tid & 15, ty = tid >> 4;
    const int bh = blockIdx.x;
    const int b  = bh >> 3, h = bh & 7;
    const int q0 = blockIdx.y << 6;

    const int lr  = tid >> 2;          // 0..63
    const int lc0 = (tid & 3) << 4;    // 16 cols per thread via 4x float4

    // Load Q tile [64 q][64 d]
    {
        const float* src = qkv + (size_t)(b*SEQ + q0 + lr) * QKVC + h*HD;
        #pragma unroll
        for (int v = 0; v < 4; v++) {
            float4 t4 = *(const float4*)(src + lc0 + v*4);
            Qs[lr*65 + lc0 + v*4 + 0] = t4.x;
            Qs[lr*65 + lc0 + v*4 + 1] = t4.y;
            Qs[lr*65 + lc0 + v*4 + 2] = t4.z;
            Qs[lr*65 + lc0 + v*4 + 3] = t4.w;
        }
    }

    float o[4][4] = {};
    float m_r[4], l_r[4];
    #pragma unroll
    for (int i = 0; i < 4; i++) { m_r[i] = NEG_MAX; l_r[i] = 0.f; }

    for (int k0 = 0; k0 < SEQ; k0 += 64) {
        __syncthreads();   // prior iter's readers of Ks/Vs/Ps done (and Qs visible, iter 0)
        // Load K, V tiles
        {
            const float* ksrc = qkv + (size_t)(b*SEQ + k0 + lr) * QKVC + DIMC   + h*HD;
            const float* vsrc = qkv + (size_t)(b*SEQ + k0 + lr) * QKVC + 2*DIMC + h*HD;
            #pragma unroll
            for (int v = 0; v < 4; v++) {
                float4 kt = *(const float4*)(ksrc + lc0 + v*4);
                float4 vt = *(const float4*)(vsrc + lc0 + v*4);
                Ks[lr*65 + lc0 + v*4 + 0] = kt.x; Ks[lr*65 + lc0 + v*4 + 1] = kt.y;
                Ks[lr*65 + lc0 + v*4 + 2] = kt.z; Ks[lr*65 + lc0 + v*4 + 3] = kt.w;
                Vs[lr*65 + lc0 + v*4 + 0] = vt.x; Vs[lr*65 + lc0 + v*4 + 1] = vt.y;
                Vs[lr*65 + lc0 + v*4 + 2] = vt.z; Vs[lr*65 + lc0 + v*4 + 3] = vt.w;
            }
        }
        __syncthreads();

        // S = Q K^T  (4x4 per thread)
        float s[4][4] = {};
        #pragma unroll
        for (int d = 0; d < 64; d++) {
            float a[4], bb[4];
            #pragma unroll
            for (int i = 0; i < 4; i++) a[i]  = Qs[(ty*4+i)*65 + d];
            #pragma unroll
            for (int j = 0; j < 4; j++) bb[j] = Ks[(tx*4+j)*65 + d];
            #pragma unroll
            for (int i = 0; i < 4; i++)
                #pragma unroll
                for (int j = 0; j < 4; j++)
                    s[i][j] = fmaf(a[i], bb[j], s[i][j]);
        }

        // scale + mask (mask is int32 per harness dtype rules: bool -> int32)
        #pragma unroll
        for (int i = 0; i < 4; i++) {
            const int q = q0 + ty*4 + i;
            int4 mb = *(const int4*)(mask + (size_t)(b*SEQ + q) * SEQ + k0 + tx*4);
            s[i][0] = mb.x ? NEG_MAX : s[i][0] * ATT_SCALE;
            s[i][1] = mb.y ? NEG_MAX : s[i][1] * ATT_SCALE;
            s[i][2] = mb.z ? NEG_MAX : s[i][2] * ATT_SCALE;
            s[i][3] = mb.w ? NEG_MAX : s[i][3] * ATT_SCALE;
        }

        // online softmax: row max (reduce over 16 tx lanes within half-warp)
        #pragma unroll
        for (int i = 0; i < 4; i++) {
            float mt = fmaxf(fmaxf(s[i][0], s[i][1]), fmaxf(s[i][2], s[i][3]));
            #pragma unroll
            for (int off = 8; off >= 1; off >>= 1)
                mt = fmaxf(mt, __shfl_xor_sync(0xffffffffu, mt, off));
            float mn = fmaxf(m_r[i], mt);
            float alpha = __expf(m_r[i] - mn);
            m_r[i] = mn;

            float rs = 0.f;
            #pragma unroll
            for (int j = 0; j < 4; j++) {
                s[i][j] = __expf(s[i][j] - mn);
                rs += s[i][j];
            }
            #pragma unroll
            for (int off = 8; off >= 1; off >>= 1)
                rs += __shfl_xor_sync(0xffffffffu, rs, off);
            l_r[i] = l_r[i] * alpha + rs;
            #pragma unroll
            for (int j = 0; j < 4; j++) {
                o[i][j] *= alpha;
                Ps[(ty*4+i)*65 + tx*4 + j] = s[i][j];
            }
        }
        __syncthreads();

        // O += P @ V
        #pragma unroll 8
        for (int kk = 0; kk < 64; kk++) {
            float p[4], vv[4];
            #pragma unroll
            for (int i = 0; i < 4; i++) p[i]  = Ps[(ty*4+i)*65 + kk];
            #pragma unroll
            for (int j = 0; j < 4; j++) vv[j] = Vs[kk*65 + tx*4 + j];
            #pragma unroll
            for (int i = 0; i < 4; i++)
                #pragma unroll
                for (int j = 0; j < 4; j++)
                    o[i][j] = fmaf(p[i], vv[j], o[i][j]);
        }
    }

    // normalize + write: out[b, q, h*HD + d]
    #pragma unroll
    for (int i = 0; i < 4; i++) {
        float inv = 1.0f / l_r[i];
        const size_t rowoff = (size_t)(b*SEQ + q0 + ty*4 + i) * DIMC + h*HD + tx*4;
        #pragma unroll
        for (int j = 0; j < 4; j++)
            out[rowoff + j] = o[i][j] * inv;
    }
}

// ---------------------------------------------------------------------------
extern "C" void kernel_launch(void* const* d_in, const int* in_sizes, int n_in,
                              void* d_out, int out_size) {
    const float* x      = (const float*)d_in[0];
    const int*   mask   = (const int*)d_in[1];    // bool delivered as int32
    const float* qkv_w  = (const float*)d_in[2];
    const float* qkv_b  = (const float*)d_in[3];
    const float* proj_w = (const float*)d_in[4];
    const float* proj_b = (const float*)d_in[5];
    float*       out    = (float*)d_out;

    float *qkv_buf, *att_buf;
    cudaGetSymbolAddress((void**)&qkv_buf, g_qkv);
    cudaGetSymbolAddress((void**)&att_buf, g_att);

    // 1) QKV projection: [8192,512] @ [1536,512]^T + b
    {
        dim3 grid(ROWS / 64, QKVC / 64);
        gemm_bias_kernel<<<grid, 256>>>(x, qkv_w, qkv_b, qkv_buf, ROWS, QKVC, DIMC);
    }

    // 2) masked flash attention
    {
        const int smem = 4 * 64 * 65 * (int)sizeof(float);  // 66560 B
        cudaFuncSetAttribute(attn_kernel, cudaFuncAttributeMaxDynamicSharedMemorySize, smem);
        dim3 grid(BATCH * NH, SEQ / 64);
        attn_kernel<<<grid, 256, smem>>>(qkv_buf, mask, att_buf);
    }

    // 3) output projection: [8192,512] @ [512,512]^T + b
    {
        dim3 grid(ROWS / 64, DIMC / 64);
        gemm_bias_kernel<<<grid, 256>>>(att_buf, proj_w, proj_b, out, ROWS, DIMC, DIMC);
    }
}

// round 3
// speedup vs baseline: 2.1381x; 2.1381x over previous
#include <cuda_runtime.h>
#include <math.h>

#define BATCH 8
#define SEQ   1024
#define DIMC  512
#define NH    8
#define HD    64
#define ROWS  (BATCH*SEQ)           // 8192
#define QKVC  (3*DIMC)              // 1536
#define ATT_SCALE 0.125f            // HD^-0.5
#define NEG_MAX (-3.402823466e38f)  // float32 finfo.min

// Scratch (allocation-free rule: __device__ globals)
__device__ float g_qkv[(size_t)ROWS * QKVC];   // [8192, 1536]
__device__ float g_att[(size_t)ROWS * DIMC];   // [8192, 512]  (b,t, h*d)

// ---------------------------------------------------------------------------
// Helpers: tf32 rounding + m16n8k8 tf32 MMA
// ---------------------------------------------------------------------------
__device__ __forceinline__ float tf32f(float x) {
    unsigned u;
    asm("cvt.rna.tf32.f32 %0, %1;" : "=r"(u) : "f"(x));
    return __uint_as_float(u);
}

__device__ __forceinline__ void mma_tf32(float d[4], const unsigned a[4],
                                         unsigned b0, unsigned b1) {
    asm volatile("mma.sync.aligned.m16n8k8.row.col.f32.tf32.tf32.f32 "
                 "{%0,%1,%2,%3}, {%4,%5,%6,%7}, {%8,%9}, {%0,%1,%2,%3};"
                 : "+f"(d[0]), "+f"(d[1]), "+f"(d[2]), "+f"(d[3])
                 : "r"(a[0]), "r"(a[1]), "r"(a[2]), "r"(a[3]),
                   "r"(b0), "r"(b1));
}

// ---------------------------------------------------------------------------
// C[M,N] = A[M,K] @ W[N,K]^T + bias[N]     (tf32 tensor-core)
// Block tile 128x128, BK=32, 256 threads (8 warps, each 32x64).
// SMEM row stride 36 floats -> fragment LDS bank = 4*(lane>>2)+(lane&3), unique.
// ---------------------------------------------------------------------------
__global__ __launch_bounds__(256)
void gemm_tf32(const float* __restrict__ A,
               const float* __restrict__ W,
               const float* __restrict__ bias,
               float* __restrict__ C,
               int M, int N, int K) {
    __shared__ float As[128][36];
    __shared__ float Ws[128][36];
    const int tid  = threadIdx.x;
    const int lane = tid & 31;
    const int warp = tid >> 5;
    const int wm = warp >> 1;          // 0..3 -> rows wm*32
    const int wn = warp & 1;           // 0..1 -> cols wn*64
    const int r = lane >> 2, c = lane & 3;
    const int row0 = blockIdx.x << 7;
    const int col0 = blockIdx.y << 7;

    const int lr = tid >> 3;           // 0..31
    const int lc = (tid & 7) << 2;     // 0..28

    const float* Aptr = A + (size_t)(row0 + lr) * K + lc;
    const float* Wptr = W + (size_t)(col0 + lr) * K + lc;

    float4 abuf[4], wbuf[4];
    #pragma unroll
    for (int i = 0; i < 4; i++) {
        abuf[i] = *(const float4*)(Aptr + (size_t)(i*32) * K);
        wbuf[i] = *(const float4*)(Wptr + (size_t)(i*32) * K);
    }

    float acc[2][8][4] = {};

    for (int k0 = 0; k0 < K; k0 += 32) {
        __syncthreads();
        #pragma unroll
        for (int i = 0; i < 4; i++) {
            float* ad = &As[lr + i*32][lc];
            ad[0]=tf32f(abuf[i].x); ad[1]=tf32f(abuf[i].y);
            ad[2]=tf32f(abuf[i].z); ad[3]=tf32f(abuf[i].w);
            float* wd = &Ws[lr + i*32][lc];
            wd[0]=tf32f(wbuf[i].x); wd[1]=tf32f(wbuf[i].y);
            wd[2]=tf32f(wbuf[i].z); wd[3]=tf32f(wbuf[i].w);
        }
        __syncthreads();
        if (k0 + 32 < K) {
            #pragma unroll
            for (int i = 0; i < 4; i++) {
                abuf[i] = *(const float4*)(Aptr + (size_t)(i*32) * K + k0 + 32);
                wbuf[i] = *(const float4*)(Wptr + (size_t)(i*32) * K + k0 + 32);
            }
        }
        #pragma unroll
        for (int kk = 0; kk < 4; kk++) {
            unsigned af[2][4];
            #pragma unroll
            for (int mt = 0; mt < 2; mt++) {
                const int mr = wm*32 + mt*16;
                af[mt][0] = __float_as_uint(As[mr + r    ][kk*8 + c    ]);
                af[mt][1] = __float_as_uint(As[mr + r + 8][kk*8 + c    ]);
                af[mt][2] = __float_as_uint(As[mr + r    ][kk*8 + c + 4]);
                af[mt][3] = __float_as_uint(As[mr + r + 8][kk*8 + c + 4]);
            }
            #pragma unroll
            for (int nt = 0; nt < 8; nt++) {
                const int nc = wn*64 + nt*8;
                unsigned b0 = __float_as_uint(Ws[nc + r][kk*8 + c    ]);
                unsigned b1 = __float_as_uint(Ws[nc + r][kk*8 + c + 4]);
                mma_tf32(acc[0][nt], af[0], b0, b1);
                mma_tf32(acc[1][nt], af[1], b0, b1);
            }
        }
    }

    // epilogue: c0,c1 = (row, 2c/2c+1), c2,c3 = (row+8, ...)
    #pragma unroll
    for (int mt = 0; mt < 2; mt++) {
        const int rw = row0 + wm*32 + mt*16 + r;
        #pragma unroll
        for (int nt = 0; nt < 8; nt++) {
            const int cl = col0 + wn*64 + nt*8 + 2*c;
            const float b0 = bias[cl], b1 = bias[cl+1];
            float2 v0 = make_float2(acc[mt][nt][0] + b0, acc[mt][nt][1] + b1);
            float2 v1 = make_float2(acc[mt][nt][2] + b0, acc[mt][nt][3] + b1);
            *(float2*)(C + (size_t)rw * N + cl)       = v0;
            *(float2*)(C + (size_t)(rw+8) * N + cl)   = v1;
        }
    }
}

// ---------------------------------------------------------------------------
// Flash attention, tf32 tensor-core. Block = 128 threads (4 warps), 64 queries
// of one (b,h). Warp w owns q rows [w*16, w*16+16). K stored d-major (stride
// 72), V stride 76, Q/P stride 68 -> all fragment LDS conflict-free.
// Mask int32 != 0 -> -FLT_MAX pre-softmax (all-masked row -> uniform, as ref).
// ---------------------------------------------------------------------------
__global__ __launch_bounds__(128)
void attn_tf32(const float* __restrict__ qkv,
               const int* __restrict__ mask,
               float* __restrict__ out) {
    extern __shared__ float sm[];
    float* Qs = sm;                  // [64][68]
    float* Kt = Qs + 64*68;          // [64][72]  Kt[d][key]
    float* Vs = Kt + 64*72;          // [64][76]  Vs[key][d]
    float* Ps = Vs + 64*76;          // [64][68]

    const int tid  = threadIdx.x;
    const int lane = tid & 31;
    const int warp = tid >> 5;
    const int b = blockIdx.x >> 3, h = blockIdx.x & 7;
    const int q0 = blockIdx.y << 6;
    const int r = lane >> 2, c = lane & 3;

    const int ldq = tid & 63;            // row within 64-row tile
    const int ldh = (tid >> 6) << 5;     // 0 or 32 (d-half)

    // ---- Q tile -> tf32 smem
    {
        const float* src = qkv + (size_t)(b*SEQ + q0 + ldq)*QKVC + h*HD + ldh;
        #pragma unroll
        for (int v = 0; v < 8; v++) {
            float4 t4 = *(const float4*)(src + v*4);
            float* dst = Qs + ldq*68 + ldh + v*4;
            dst[0]=tf32f(t4.x); dst[1]=tf32f(t4.y); dst[2]=tf32f(t4.z); dst[3]=tf32f(t4.w);
        }
    }
    __syncthreads();

    // ---- Q fragments, register-resident across all key tiles
    unsigned qf[8][4];
    {
        const int mr = warp*16;
        #pragma unroll
        for (int kk = 0; kk < 8; kk++) {
            qf[kk][0] = __float_as_uint(Qs[(mr + r    )*68 + kk*8 + c    ]);
            qf[kk][1] = __float_as_uint(Qs[(mr + r + 8)*68 + kk*8 + c    ]);
            qf[kk][2] = __float_as_uint(Qs[(mr + r    )*68 + kk*8 + c + 4]);
            qf[kk][3] = __float_as_uint(Qs[(mr + r + 8)*68 + kk*8 + c + 4]);
        }
    }

    float o[8][4] = {};
    float m0 = NEG_MAX, m1 = NEG_MAX, l0 = 0.f, l1 = 0.f;
    const int qrow0 = q0 + warp*16 + r;
    const size_t mrow0 = (size_t)(b*SEQ + qrow0) * SEQ;
    const size_t mrow1 = mrow0 + (size_t)8 * SEQ;

    for (int k0 = 0; k0 < SEQ; k0 += 64) {
        __syncthreads();
        // ---- load K (transposed, d-major) and V
        {
            const float* ksrc = qkv + (size_t)(b*SEQ + k0 + ldq)*QKVC + DIMC + h*HD + ldh;
            const float* vsrc = ksrc + DIMC;
            #pragma unroll
            for (int v = 0; v < 8; v++) {
                float4 k4 = *(const float4*)(ksrc + v*4);
                Kt[(ldh + v*4 + 0)*72 + ldq] = tf32f(k4.x);
                Kt[(ldh + v*4 + 1)*72 + ldq] = tf32f(k4.y);
                Kt[(ldh + v*4 + 2)*72 + ldq] = tf32f(k4.z);
                Kt[(ldh + v*4 + 3)*72 + ldq] = tf32f(k4.w);
                float4 v4d = *(const float4*)(vsrc + v*4);
                float* vd = Vs + ldq*76 + ldh + v*4;
                vd[0]=tf32f(v4d.x); vd[1]=tf32f(v4d.y); vd[2]=tf32f(v4d.z); vd[3]=tf32f(v4d.w);
            }
        }
        __syncthreads();

        // ---- S = Q K^T  (per warp: 16 q x 64 keys)
        float s[8][4] = {};
        #pragma unroll
        for (int kk = 0; kk < 8; kk++) {
            #pragma unroll
            for (int nt = 0; nt < 8; nt++) {
                unsigned b0 = __float_as_uint(Kt[(kk*8 + c    )*72 + nt*8 + r]);
                unsigned b1 = __float_as_uint(Kt[(kk*8 + c + 4)*72 + nt*8 + r]);
                mma_tf32(s[nt], qf[kk], b0, b1);
            }
        }

        // ---- mask + scale
        #pragma unroll
        for (int nt = 0; nt < 8; nt++) {
            const int kc = k0 + nt*8 + 2*c;
            int2 mv0 = *(const int2*)(mask + mrow0 + kc);
            int2 mv1 = *(const int2*)(mask + mrow1 + kc);
            s[nt][0] = mv0.x ? NEG_MAX : s[nt][0]*ATT_SCALE;
            s[nt][1] = mv0.y ? NEG_MAX : s[nt][1]*ATT_SCALE;
            s[nt][2] = mv1.x ? NEG_MAX : s[nt][2]*ATT_SCALE;
            s[nt][3] = mv1.y ? NEG_MAX : s[nt][3]*ATT_SCALE;
        }

        // ---- online softmax (rows r and r+8; row spread over the 4 quad lanes)
        float mt0 = NEG_MAX, mt1 = NEG_MAX;
        #pragma unroll
        for (int nt = 0; nt < 8; nt++) {
            mt0 = fmaxf(mt0, fmaxf(s[nt][0], s[nt][1]));
            mt1 = fmaxf(mt1, fmaxf(s[nt][2], s[nt][3]));
        }
        mt0 = fmaxf(mt0, __shfl_xor_sync(0xffffffffu, mt0, 1));
        mt0 = fmaxf(mt0, __shfl_xor_sync(0xffffffffu, mt0, 2));
        mt1 = fmaxf(mt1, __shfl_xor_sync(0xffffffffu, mt1, 1));
        mt1 = fmaxf(mt1, __shfl_xor_sync(0xffffffffu, mt1, 2));

        const float mn0 = fmaxf(m0, mt0), mn1 = fmaxf(m1, mt1);
        const float a0 = __expf(m0 - mn0), a1 = __expf(m1 - mn1);
        m0 = mn0; m1 = mn1;

        float rs0 = 0.f, rs1 = 0.f;
        #pragma unroll
        for (int nt = 0; nt < 8; nt++) {
            s[nt][0] = __expf(s[nt][0] - mn0);
            s[nt][1] = __expf(s[nt][1] - mn0);
            s[nt][2] = __expf(s[nt][2] - mn1);
            s[nt][3] = __expf(s[nt][3] - mn1);
            rs0 += s[nt][0] + s[nt][1];
            rs1 += s[nt][2] + s[nt][3];
        }
        rs0 += __shfl_xor_sync(0xffffffffu, rs0, 1);
        rs0 += __shfl_xor_sync(0xffffffffu, rs0, 2);
        rs1 += __shfl_xor_sync(0xffffffffu, rs1, 1);
        rs1 += __shfl_xor_sync(0xffffffffu, rs1, 2);
        l0 = l0*a0 + rs0;
        l1 = l1*a1 + rs1;

        // ---- rescale O, store P (tf32) to per-warp-private smem
        const int pr0 = warp*16 + r;
        #pragma unroll
        for (int nt = 0; nt < 8; nt++) {
            o[nt][0] *= a0; o[nt][1] *= a0; o[nt][2] *= a1; o[nt][3] *= a1;
            *(float2*)(Ps + (pr0    )*68 + nt*8 + 2*c) = make_float2(tf32f(s[nt][0]), tf32f(s[nt][1]));
            *(float2*)(Ps + (pr0 + 8)*68 + nt*8 + 2*c) = make_float2(tf32f(s[nt][2]), tf32f(s[nt][3]));
        }
        __syncwarp();

        // ---- O += P V
        #pragma unroll
        for (int kk = 0; kk < 8; kk++) {
            unsigned pf[4];
            pf[0] = __float_as_uint(Ps[(pr0    )*68 + kk*8 + c    ]);
            pf[1] = __float_as_uint(Ps[(pr0 + 8)*68 + kk*8 + c    ]);
            pf[2] = __float_as_uint(Ps[(pr0    )*68 + kk*8 + c + 4]);
            pf[3] = __float_as_uint(Ps[(pr0 + 8)*68 + kk*8 + c + 4]);
            #pragma unroll
            for (int nt = 0; nt < 8; nt++) {
                unsigned b0 = __float_as_uint(Vs[(kk*8 + c    )*76 + nt*8 + r]);
                unsigned b1 = __float_as_uint(Vs[(kk*8 + c + 4)*76 + nt*8 + r]);
                mma_tf32(o[nt], pf, b0, b1);
            }
        }
    }

    // ---- normalize + write out[b, q, h*HD + d]
    const float inv0 = 1.0f / l0, inv1 = 1.0f / l1;
    float* orow = out + (size_t)(b*SEQ + qrow0)*DIMC + h*HD;
    #pragma unroll
    for (int nt = 0; nt < 8; nt++) {
        *(float2*)(orow + nt*8 + 2*c)            = make_float2(o[nt][0]*inv0, o[nt][1]*inv0);
        *(float2*)(orow + (size_t)8*DIMC + nt*8 + 2*c) = make_float2(o[nt][2]*inv1, o[nt][3]*inv1);
    }
}

// ---------------------------------------------------------------------------
extern "C" void kernel_launch(void* const* d_in, const int* in_sizes, int n_in,
                              void* d_out, int out_size) {
    const float* x      = (const float*)d_in[0];
    const int*   mask   = (const int*)d_in[1];    // bool delivered as int32
    const float* qkv_w  = (const float*)d_in[2];
    const float* qkv_b  = (const float*)d_in[3];
    const float* proj_w = (const float*)d_in[4];
    const float* proj_b = (const float*)d_in[5];
    float*       out    = (float*)d_out;

    float *qkv_buf, *att_buf;
    cudaGetSymbolAddress((void**)&qkv_buf, g_qkv);
    cudaGetSymbolAddress((void**)&att_buf, g_att);

    // 1) QKV projection: [8192,512] @ [1536,512]^T + b
    {
        dim3 grid(ROWS / 128, QKVC / 128);
        gemm_tf32<<<grid, 256>>>(x, qkv_w, qkv_b, qkv_buf, ROWS, QKVC, DIMC);
    }

    // 2) masked flash attention (tf32 tensor cores)
    {
        const int smem = (64*68 + 64*72 + 64*76 + 64*68) * (int)sizeof(float); // 72.7 KB
        cudaFuncSetAttribute(attn_tf32, cudaFuncAttributeMaxDynamicSharedMemorySize, smem);
        dim3 grid(BATCH * NH, SEQ / 64);
        attn_tf32<<<grid, 128, smem>>>(qkv_buf, mask, att_buf);
    }

    // 3) output projection: [8192,512] @ [512,512]^T + b
    {
        dim3 grid(ROWS / 128, DIMC / 128);
        gemm_tf32<<<grid, 256>>>(att_buf, proj_w, proj_b, out, ROWS, DIMC, DIMC);
    }
}